// round 9
// baseline (speedup 1.0000x reference)
#include <cuda_runtime.h>

// HybridQuanvolutionFraudNet: reference output = log_softmax(logits, axis=-1)
// with logits of shape [B, 1]. log_softmax over a size-1 axis is identically
// 0.0 (shifted = x - max = 0; logsumexp(0) = 0). All upstream computation
// (quanvolution 4-qubit statevector sim, tanh MLP, final linear) is dead.
// Output = zeros(out_size, float32). Verified rel_err = 0.0 bitwise (R1,R3,R4).
//
// History:
//   R1: grid=2 block=256 kernel  -> wall 4.58 µs, ncu kernel 3.360 µs
//   R3: graph memset node        -> wall 5.50 µs (worse or noise; reverted)
//   R4: grid=1 block=512 kernel  -> wall 5.54 µs, ncu kernel 3.392 µs
//   R5-R8: infra acquisition timeouts — this kernel has not yet run.
// ncu kernel time is grid-invariant => pure launch/drain constant. Wall time
// varies ±~1 µs run-to-run, exceeding any controllable delta. Minimal
// 1-CTA / 4-warp variant; if kernel time stays ~3.4 µs, the floor is
// confirmed launch-latency-bound and this kernel is final.

__global__ void zero_out_128(float4* __restrict__ out) {
    // grid=1, block=128: each thread writes 4 consecutive float4 (64 B).
    // 128 * 64 B = 8192 B = 2048 floats, exact fit for out_size == 2048.
    const float4 z = make_float4(0.f, 0.f, 0.f, 0.f);
    int i = threadIdx.x * 4;
    out[i + 0] = z;
    out[i + 1] = z;
    out[i + 2] = z;
    out[i + 3] = z;
}

__global__ void zero_out_generic(float* __restrict__ out, int n) {
    int i = blockIdx.x * blockDim.x + threadIdx.x;
    if (i < n) out[i] = 0.f;
}

extern "C" void kernel_launch(void* const* d_in, const int* in_sizes, int n_in,
                              void* d_out, int out_size) {
    (void)d_in; (void)in_sizes; (void)n_in;
    if (out_size == 2048) {
        zero_out_128<<<1, 128>>>((float4*)d_out);
    } else {
        int block = 256;
        int grid = (out_size + block - 1) / block;
        zero_out_generic<<<grid, block>>>((float*)d_out, out_size);
    }
}

// round 10
// speedup vs baseline: 3.4722x; 3.4722x over previous
#include <cuda_runtime.h>

// HybridQuanvolutionFraudNet: reference output = log_softmax(logits, axis=-1)
// with logits of shape [B, 1]. log_softmax over a size-1 axis is identically
// 0.0 (shifted = x - max = 0; logsumexp(0) = 0). All upstream computation
// (quanvolution 4-qubit statevector sim, tanh MLP, final linear) is dead.
// Output = zeros(out_size, float32). Verified rel_err = 0.0 bitwise (R1,R3,R4,R9).
//
// Measured (ncu kernel time is grid-invariant => launch/drain floor):
//   R1: grid=2 block=256 -> wall  4.58 µs, ncu 3.360 µs   <- best draw
//   R3: memset node      -> wall  5.50 µs                  (reverted)
//   R4: grid=1 block=512 -> wall  5.54 µs, ncu 3.392 µs
//   R9: grid=1 block=128 -> wall 16.00 µs, ncu 3.520 µs   (contended machine)
// Wall time is dominated by machine contention (up to ~3x swings); kernel
// time is a fixed ~3.4 µs launch envelope with all pipes at 0.0%. This is
// the floor. Pinning the empirically-best config: grid=2, block=256,
// branchless exact-fit float4 stores.

__global__ void zero_out(float4* __restrict__ out) {
    // grid=2, block=256: 512 threads x 16B = 8192 B = 2048 floats, exact fit.
    out[blockIdx.x * 256 + threadIdx.x] = make_float4(0.f, 0.f, 0.f, 0.f);
}

__global__ void zero_out_generic(float* __restrict__ out, int n) {
    int i = blockIdx.x * blockDim.x + threadIdx.x;
    if (i < n) out[i] = 0.f;
}

extern "C" void kernel_launch(void* const* d_in, const int* in_sizes, int n_in,
                              void* d_out, int out_size) {
    (void)d_in; (void)in_sizes; (void)n_in;
    if (out_size == 2048) {
        zero_out<<<2, 256>>>((float4*)d_out);
    } else {
        int block = 256;
        int grid = (out_size + block - 1) / block;
        zero_out_generic<<<grid, block>>>((float*)d_out, out_size);
    }
}